// round 3
// baseline (speedup 1.0000x reference)
#include <cuda_runtime.h>
#include <math.h>

// ---------------------------------------------------------------------------
// DBASolver: Schur-complement pose/depth update. B=16, N=131072, C=2, P=6.
// Pass 1: per-node H_pd/g_d/inv_H_dd -> scratch; reduce 27 per-batch scalars.
// Pass 2: single block: finish reduction, dampen, 6x6 solve, write pose.
// Pass 3: delta_depth = inv_H_dd * (g_d - H_pd . pose), clip, write.
// ---------------------------------------------------------------------------

#define MAXB 16
#define MAXN 131072
#define ITER 8
#define TPB  256
#define MAXCHUNKS 256

// per-node scratch: {hpd0..3} {hpd4,hpd5,g_d,inv}
__device__ float4 g_scratch[(size_t)MAXB * MAXN * 2];
__device__ float  g_partial[(size_t)MAXB * MAXCHUNKS * 27];
__device__ float  g_pose[MAXB * 6];
__device__ int    g_nanflag;

// ---- per-node body -------------------------------------------------------
__device__ __forceinline__ void node_body(
    size_t idx, float safe_l,
    const float4* __restrict__ Jp4, const float2* __restrict__ r2,
    const float2* __restrict__ w2,  const float2* __restrict__ jd2,
    float acc[27])
{
    float4 jpA = __ldcs(&Jp4[idx * 3 + 0]);
    float4 jpB = __ldcs(&Jp4[idx * 3 + 1]);
    float4 jpC = __ldcs(&Jp4[idx * 3 + 2]);
    float2 rv  = __ldcs(&r2[idx]);
    float2 wv  = __ldcs(&w2[idx]);
    float2 jdv = __ldcs(&jd2[idx]);

    float conf = wv.x, nl = wv.y;
    float jp0[6] = { jpA.x, jpA.y, jpA.z, jpA.w, jpB.x, jpB.y };
    float jp1[6] = { jpB.z, jpB.w, jpC.x, jpC.y, jpC.z, jpC.w };

    float hpd[6];
#pragma unroll
    for (int p = 0; p < 6; p++)
        hpd[p] = conf * (jp0[p] * jdv.x + jp1[p] * jdv.y);

    float hdd = conf * (jdv.x * jdv.x + jdv.y * jdv.y);
    float gd  = conf * (jdv.x * rv.x  + jdv.y * rv.y);
    float inv = 1.0f / fmaxf(hdd + safe_l + nl + 1e-4f, 1e-4f);

    float t[6], cjp0[6], cjp1[6];
#pragma unroll
    for (int p = 0; p < 6; p++) {
        t[p]    = inv  * hpd[p];
        cjp0[p] = conf * jp0[p];
        cjp1[p] = conf * jp1[p];
    }

    int k = 0;
#pragma unroll
    for (int p = 0; p < 6; p++) {
#pragma unroll
        for (int q = p; q < 6; q++) {
            float a = acc[k];
            a = fmaf(cjp0[p], jp0[q], a);
            a = fmaf(cjp1[p], jp1[q], a);
            a = fmaf(-t[p],   hpd[q], a);
            acc[k++] = a;
        }
    }
#pragma unroll
    for (int p = 0; p < 6; p++) {
        float gp = conf * (jp0[p] * rv.x + jp1[p] * rv.y);
        acc[21 + p] += gp - t[p] * gd;
    }

    g_scratch[idx * 2 + 0] = make_float4(hpd[0], hpd[1], hpd[2], hpd[3]);
    g_scratch[idx * 2 + 1] = make_float4(hpd[4], hpd[5], gd, inv);
}

__global__ void __launch_bounds__(TPB, 4)
pass1_kernel(const float* __restrict__ r, const float* __restrict__ w,
             const float* __restrict__ Jp, const float* __restrict__ Jd,
             const float* __restrict__ lmbda, int N)
{
    const int b = blockIdx.y;
    const size_t bn0 = (size_t)b * N;
    const size_t base = (size_t)blockIdx.x * (TPB * ITER);

    float lm = lmbda[b];
    float safe_l = isnan(lm) ? 100.0f : lm;
    safe_l = fmaxf(safe_l, 0.001f);

    const float4* __restrict__ Jp4 = (const float4*)Jp;
    const float2* __restrict__ r2  = (const float2*)r;
    const float2* __restrict__ w2  = (const float2*)w;
    const float2* __restrict__ jd2 = (const float2*)Jd;

    float acc[27];
#pragma unroll
    for (int i = 0; i < 27; i++) acc[i] = 0.0f;

    if (base + (size_t)(TPB * ITER) <= (size_t)N) {
        // full tile: no per-iteration guard -> compiler can batch/pipeline loads
#pragma unroll
        for (int it = 0; it < ITER; it++) {
            size_t n = base + (size_t)it * TPB + threadIdx.x;
            node_body(bn0 + n, safe_l, Jp4, r2, w2, jd2, acc);
        }
    } else {
#pragma unroll
        for (int it = 0; it < ITER; it++) {
            size_t n = base + (size_t)it * TPB + threadIdx.x;
            if (n < (size_t)N)
                node_body(bn0 + n, safe_l, Jp4, r2, w2, jd2, acc);
        }
    }

    // warp reduce 27 values
#pragma unroll
    for (int i = 0; i < 27; i++) {
#pragma unroll
        for (int off = 16; off > 0; off >>= 1)
            acc[i] += __shfl_down_sync(0xFFFFFFFFu, acc[i], off);
    }

    __shared__ float sred[TPB / 32][27];
    int warp = threadIdx.x >> 5, lane = threadIdx.x & 31;
    if (lane == 0) {
#pragma unroll
        for (int i = 0; i < 27; i++) sred[warp][i] = acc[i];
    }
    __syncthreads();

    if (threadIdx.x < 27) {
        float s = 0.0f;
#pragma unroll
        for (int wd = 0; wd < TPB / 32; wd++) s += sred[wd][threadIdx.x];
        g_partial[((size_t)b * gridDim.x + blockIdx.x) * 27 + threadIdx.x] = s;
    }
}

__global__ void __launch_bounds__(512)
solve_kernel(const float* __restrict__ lmbda, const int* __restrict__ iter_idx,
             float* __restrict__ out, int B, int nchunks)
{
    __shared__ float sH[MAXB][27];
    __shared__ int   s_nan;
    int t = threadIdx.x;
    if (t == 0) s_nan = 0;

    if (t < B * 27) {
        int b = t / 27, i = t % 27;
        float s = 0.0f;
        for (int c = 0; c < nchunks; c++)
            s += g_partial[((size_t)b * nchunks + c) * 27 + i];
        sH[b][i] = s;
    }
    __syncthreads();

    float pose[6];
    int b = t;
    if (b < B) {
        float lm = lmbda[b];
        float safe_l = isnan(lm) ? 100.0f : lm;
        safe_l = fmaxf(safe_l, 0.001f);

        float H[6][6], g[6];
        int k = 0;
        for (int p = 0; p < 6; p++)
            for (int q = p; q < 6; q++) { float v = sH[b][k++]; H[p][q] = v; H[q][p] = v; }
        for (int p = 0; p < 6; p++) g[p] = sH[b][21 + p];

        for (int i = 0; i < 6; i++) H[i][i] += safe_l;

        int iters = iter_idx[0];
        if (iters >= 2) {
            for (int p = 3; p < 6; p++) g[p] = 0.0f;
            for (int p = 3; p < 6; p++)
                for (int q = 3; q < 6; q++) H[p][q] += 1.0e8f;
        }
        for (int i = 0; i < 6; i++) H[i][i] += 1.0f;
        for (int i = 0; i < 6; i++) H[i][i] += 0.01f * H[i][i];

        // 6x6 solve in double, partial pivoting
        double A[6][7];
        for (int i = 0; i < 6; i++) {
            for (int j = 0; j < 6; j++) A[i][j] = (double)H[i][j];
            A[i][6] = (double)g[i];
        }
        for (int c = 0; c < 6; c++) {
            int piv = c; double mx = fabs(A[c][c]);
            for (int rr = c + 1; rr < 6; rr++) {
                double a = fabs(A[rr][c]);
                if (a > mx) { mx = a; piv = rr; }
            }
            if (piv != c) {
                for (int j = c; j < 7; j++) {
                    double tmp = A[c][j]; A[c][j] = A[piv][j]; A[piv][j] = tmp;
                }
            }
            double d = A[c][c];
            for (int rr = c + 1; rr < 6; rr++) {
                double f = A[rr][c] / d;
                for (int j = c; j < 7; j++) A[rr][j] -= f * A[c][j];
            }
        }
        double x[6];
        for (int i = 5; i >= 0; i--) {
            double s = A[i][6];
            for (int j = i + 1; j < 6; j++) s -= A[i][j] * x[j];
            x[i] = s / A[i][i];
        }

        bool anynan = false;
        for (int p = 0; p < 6; p++) {
            pose[p] = (float)x[p];
            g_pose[b * 6 + p] = pose[p];
            if (isnan(pose[p])) anynan = true;
        }
        if (anynan) atomicOr(&s_nan, 1);
    }
    __syncthreads();

    if (t == 0) g_nanflag = s_nan;
    if (b < B) {
        for (int p = 0; p < 6; p++) {
            float v = fminf(fmaxf(pose[p], -2.0f), 2.0f);
            out[b * 6 + p] = s_nan ? 0.0f : v;
        }
    }
}

#define DPT 4   // nodes per thread in depth pass

__global__ void __launch_bounds__(TPB)
depth_kernel(float* __restrict__ out, int N, int B)
{
    size_t total = (size_t)B * N;
    size_t i0 = ((size_t)blockIdx.x * TPB + threadIdx.x) * DPT;
    if (i0 >= total) return;

    int nanf = g_nanflag;
    float dd[DPT];

    bool grouped = ((N & (DPT - 1)) == 0);
    int b_grp = grouped ? (int)(i0 / (size_t)N) : 0;
    float pg[6];
    if (grouped) {
#pragma unroll
        for (int p = 0; p < 6; p++) pg[p] = g_pose[b_grp * 6 + p];
    }

#pragma unroll
    for (int kk = 0; kk < DPT; kk++) {
        size_t idx = i0 + kk;
        if (idx >= total) { dd[kk] = 0.0f; continue; }

        float4 s0 = __ldcs(&g_scratch[idx * 2 + 0]);
        float4 s1 = __ldcs(&g_scratch[idx * 2 + 1]);

        float p0, p1, p2, p3, p4, p5;
        if (grouped) {
            p0 = pg[0]; p1 = pg[1]; p2 = pg[2]; p3 = pg[3]; p4 = pg[4]; p5 = pg[5];
        } else {
            int b = (int)(idx / (size_t)N);
            p0 = g_pose[b * 6 + 0]; p1 = g_pose[b * 6 + 1]; p2 = g_pose[b * 6 + 2];
            p3 = g_pose[b * 6 + 3]; p4 = g_pose[b * 6 + 4]; p5 = g_pose[b * 6 + 5];
        }

        float v = s0.x * p0 + s0.y * p1 + s0.z * p2
                + s0.w * p3 + s1.x * p4 + s1.y * p5;
        float d = s1.w * (s1.z - v);
        d = fminf(fmaxf(d, -5.0f), 5.0f);
        dd[kk] = nanf ? 0.0f : d;
    }

    float* dst = out + (size_t)B * 6 + i0;
    if (i0 + DPT <= total) {
        if ((((size_t)B * 6 + i0) & 3) == 0) {
            *(float4*)dst = make_float4(dd[0], dd[1], dd[2], dd[3]);
        } else {
#pragma unroll
            for (int kk = 0; kk < DPT; kk++) dst[kk] = dd[kk];
        }
    } else {
        for (int kk = 0; kk < DPT && i0 + kk < total; kk++) dst[kk] = dd[kk];
    }
}

extern "C" void kernel_launch(void* const* d_in, const int* in_sizes, int n_in,
                              void* d_out, int out_size)
{
    const float* r      = (const float*)d_in[0];
    const float* w      = (const float*)d_in[1];
    const float* Jp     = (const float*)d_in[2];
    const float* Jd     = (const float*)d_in[3];
    const float* lmbda  = (const float*)d_in[4];
    const int*   iter_i = (const int*)d_in[5];
    float* out = (float*)d_out;

    int B = in_sizes[4];
    int N = in_sizes[0] / (2 * B);

    int tile   = TPB * ITER;
    int chunks = (N + tile - 1) / tile;

    dim3 g1(chunks, B);
    pass1_kernel<<<g1, TPB>>>(r, w, Jp, Jd, lmbda, N);
    solve_kernel<<<1, 512>>>(lmbda, iter_i, out, B, chunks);

    size_t total = (size_t)B * N;
    size_t tpg = (size_t)TPB * DPT;
    int blocks = (int)((total + tpg - 1) / tpg);
    depth_kernel<<<blocks, TPB>>>(out, N, B);
}